// round 5
// baseline (speedup 1.0000x reference)
#include <cuda_runtime.h>

#define N_NODES 16384
#define A_ANCH  256
#define D_LAT   32

// Duplicated precomputed operands:
//   g_M_dup[a][d] = {m, m} where m = (1/A) * (anchor_emb @ W1)[a][d]
//   g_c_dup[d]    = {c, c} where c = b[d] + (1/A)*colsum(embeds[:A]) @ W2
__device__ float2 g_M_dup[A_ANCH * D_LAT];   // 64 KB
__device__ float2 g_c_dup[D_LAT];

// ---------------------------------------------------------------------------
// Kernel 1: precompute. Grid = 9 blocks x 256 threads.
// ---------------------------------------------------------------------------
__global__ __launch_bounds__(256) void precompute_kernel(
    const float* __restrict__ embeds,
    const float* __restrict__ W,       // [64,32]: W1 rows 0..31, W2 rows 32..63
    const float* __restrict__ b,       // [32]
    const int*   __restrict__ anchor_ids)
{
    __shared__ float Wsh[D_LAT * D_LAT];
    __shared__ float esh[32][32];
    __shared__ float ssh[D_LAT];

    const int t   = threadIdx.x;
    const int blk = blockIdx.x;
    const int j   = t & 31;

    if (blk < 8) {
        #pragma unroll
        for (int i = t; i < D_LAT * D_LAT; i += 256) Wsh[i] = W[i];
        for (int r = t >> 5; r < 32; r += 8) {
            int id = anchor_ids[blk * 32 + r];
            esh[r][j] = embeds[id * D_LAT + j];
        }
        __syncthreads();
        for (int r = t >> 5; r < 32; r += 8) {
            float acc = 0.f;
            #pragma unroll
            for (int d = 0; d < D_LAT; d++) acc += esh[r][d] * Wsh[d * D_LAT + j];
            float m = acc * (1.0f / 256.0f);
            g_M_dup[(blk * 32 + r) * D_LAT + j] = make_float2(m, m);
        }
    } else {
        #pragma unroll
        for (int i = t; i < D_LAT * D_LAT; i += 256) Wsh[i] = W[D_LAT * D_LAT + i];
        if (t < D_LAT) ssh[t] = 0.f;
        __syncthreads();
        {
            int grp = t >> 5;
            float part = 0.f;
            #pragma unroll 4
            for (int i = 0; i < 32; i++)
                part += embeds[(grp * 32 + i) * D_LAT + j];
            atomicAdd(&ssh[j], part);
        }
        __syncthreads();
        if (t < D_LAT) {
            float acc = 0.f;
            #pragma unroll
            for (int d = 0; d < D_LAT; d++) acc += ssh[d] * Wsh[d * D_LAT + t];
            float c = b[t] + acc * (1.0f / 256.0f);
            g_c_dup[t] = make_float2(c, c);
        }
    }
}

// ---------------------------------------------------------------------------
// Kernel 2: out[n,:] = sum_a dists[a,n] * M[a,:] + c   (n-packed f32x2)
//
// Block = 256 thr = 8 slots (8n) x 4 quarters (8d) x 8 a-groups.
// Thread tile: 4 n-pairs x 8 d = 32 packed accs. Zero packing movs:
//   dists float4 -> 2 ready f32x2 pairs; M pre-duplicated in smem.
// 64 KB dynamic smem (M_dup, then reduction). 2 blocks/SM, grid 256 = 1 wave.
// ---------------------------------------------------------------------------
__global__ __launch_bounds__(256, 2) void pnn_main_kernel(
    const float* __restrict__ dists,   // [A, N]
    float*       __restrict__ out)     // [N, D]
{
    extern __shared__ __align__(16) unsigned long long sh[];  // 8192 u64 = 64 KB

    const int t       = threadIdx.x;
    const int slot    = t & 7;
    const int quarter = (t >> 3) & 3;
    const int group   = t >> 5;
    const int n0      = blockIdx.x * 64 + slot * 8;
    const int a0      = group * 32;

    // ---- dists prefetches first (independent of precompute kernel) ----
    const float* dp = dists + (size_t)a0 * N_NODES + n0;
    float4 pfA[4], pfB[4];
    #pragma unroll
    for (int i = 0; i < 4; i++) {
        pfA[i] = *(const float4*)(dp + (size_t)i * N_NODES);
        pfB[i] = *(const float4*)(dp + (size_t)i * N_NODES + 4);
    }

    // ---- wait for precompute results (PDL) ----
    cudaGridDependencySynchronize();

    // ---- copy duplicated M (64 KB) into shared ----
    {
        const float4* src = (const float4*)g_M_dup;
        float4*       dst = (float4*)sh;
        #pragma unroll
        for (int i = 0; i < 16; i++) dst[t + 256 * i] = src[t + 256 * i];
    }
    __syncthreads();

    unsigned long long acc[32];     // [pair p 0..3][d j 0..7]
    #pragma unroll
    for (int i = 0; i < 32; i++) acc[i] = 0ULL;

    const unsigned long long* mrow = sh + (size_t)a0 * D_LAT + quarter * 8;

    #pragma unroll
    for (int it = 0; it < 32; it += 4) {
        #pragma unroll
        for (int u = 0; u < 4; u++) {
            const int step = it + u;
            float4 a = pfA[u];
            float4 bb = pfB[u];
            if (step + 4 < 32) {
                pfA[u] = *(const float4*)(dp + (size_t)(step + 4) * N_NODES);
                pfB[u] = *(const float4*)(dp + (size_t)(step + 4) * N_NODES + 4);
            }
            // 4 ready-made n-pairs, no packing needed
            unsigned long long dd0 = ((const ulonglong2*)&a)->x;
            unsigned long long dd1 = ((const ulonglong2*)&a)->y;
            unsigned long long dd2 = ((const ulonglong2*)&bb)->x;
            unsigned long long dd3 = ((const ulonglong2*)&bb)->y;

            const ulonglong2* mp = (const ulonglong2*)(mrow + step * D_LAT);
            ulonglong2 m0 = mp[0], m1 = mp[1], m2 = mp[2], m3 = mp[3];

            #define FMA8(p, dd)                                                              \
                asm("fma.rn.f32x2 %0,%1,%2,%0;" : "+l"(acc[(p)*8+0]) : "l"(dd), "l"(m0.x)); \
                asm("fma.rn.f32x2 %0,%1,%2,%0;" : "+l"(acc[(p)*8+1]) : "l"(dd), "l"(m0.y)); \
                asm("fma.rn.f32x2 %0,%1,%2,%0;" : "+l"(acc[(p)*8+2]) : "l"(dd), "l"(m1.x)); \
                asm("fma.rn.f32x2 %0,%1,%2,%0;" : "+l"(acc[(p)*8+3]) : "l"(dd), "l"(m1.y)); \
                asm("fma.rn.f32x2 %0,%1,%2,%0;" : "+l"(acc[(p)*8+4]) : "l"(dd), "l"(m2.x)); \
                asm("fma.rn.f32x2 %0,%1,%2,%0;" : "+l"(acc[(p)*8+5]) : "l"(dd), "l"(m2.y)); \
                asm("fma.rn.f32x2 %0,%1,%2,%0;" : "+l"(acc[(p)*8+6]) : "l"(dd), "l"(m3.x)); \
                asm("fma.rn.f32x2 %0,%1,%2,%0;" : "+l"(acc[(p)*8+7]) : "l"(dd), "l"(m3.y));
            FMA8(0, dd0)
            FMA8(1, dd1)
            FMA8(2, dd2)
            FMA8(3, dd3)
            #undef FMA8
        }
    }

    // ---- log2 tree reduction over the 8 a-groups (reuse sh) ----
    __syncthreads();
    #pragma unroll
    for (int s = 128; s >= 32; s >>= 1) {
        if (t >= s && t < 2 * s) {
            #pragma unroll
            for (int i = 0; i < 32; i++) sh[i * s + (t - s)] = acc[i];
        }
        __syncthreads();
        if (t < s) {
            #pragma unroll
            for (int i = 0; i < 32; i++)
                asm("add.rn.f32x2 %0,%0,%1;" : "+l"(acc[i]) : "l"(sh[i * s + t]));
        }
        __syncthreads();
    }

    // ---- epilogue: threads 0..31 (slot = t&7, quarter = t>>3) ----
    if (t < 32) {
        const int eslot = t & 7;
        const int equar = t >> 3;
        const int en0   = blockIdx.x * 64 + eslot * 8;

        const unsigned long long* c64 = (const unsigned long long*)g_c_dup;
        unsigned long long cc[8];
        #pragma unroll
        for (int k = 0; k < 8; k++) cc[k] = c64[equar * 8 + k];
        #pragma unroll
        for (int i = 0; i < 32; i++)
            asm("add.rn.f32x2 %0,%0,%1;" : "+l"(acc[i]) : "l"(cc[i & 7]));

        #pragma unroll
        for (int p = 0; p < 4; p++) {
            float lo[8], hi[8];
            #pragma unroll
            for (int j = 0; j < 8; j++)
                asm("mov.b64 {%0,%1}, %2;" : "=f"(lo[j]), "=f"(hi[j]) : "l"(acc[p * 8 + j]));
            float* r0 = out + (size_t)(en0 + 2 * p)     * D_LAT + equar * 8;
            float* r1 = out + (size_t)(en0 + 2 * p + 1) * D_LAT + equar * 8;
            *(float4*)(r0)     = make_float4(lo[0], lo[1], lo[2], lo[3]);
            *(float4*)(r0 + 4) = make_float4(lo[4], lo[5], lo[6], lo[7]);
            *(float4*)(r1)     = make_float4(hi[0], hi[1], hi[2], hi[3]);
            *(float4*)(r1 + 4) = make_float4(hi[4], hi[5], hi[6], hi[7]);
        }
    }
}

extern "C" void kernel_launch(void* const* d_in, const int* in_sizes, int n_in,
                              void* d_out, int out_size)
{
    const float* embeds     = (const float*)d_in[0];
    const float* dists      = (const float*)d_in[1];
    const float* W_hidden   = (const float*)d_in[2];
    const float* b_hidden   = (const float*)d_in[3];
    const int*   anchor_ids = (const int*)  d_in[4];
    float*       out        = (float*)d_out;

    static int smem_set = 0;
    if (!smem_set) {
        cudaFuncSetAttribute(pnn_main_kernel,
                             cudaFuncAttributeMaxDynamicSharedMemorySize, 65536);
        smem_set = 1;
    }

    precompute_kernel<<<9, 256>>>(embeds, W_hidden, b_hidden, anchor_ids);

    cudaLaunchConfig_t cfg = {};
    cfg.gridDim  = dim3(N_NODES / 64, 1, 1);
    cfg.blockDim = dim3(256, 1, 1);
    cfg.dynamicSmemBytes = 65536;
    cfg.stream = 0;
    cudaLaunchAttribute attr[1];
    attr[0].id = cudaLaunchAttributeProgrammaticStreamSerialization;
    attr[0].val.programmaticStreamSerializationAllowed = 1;
    cfg.attrs = attr;
    cfg.numAttrs = 1;

    cudaError_t e = cudaLaunchKernelEx(&cfg, pnn_main_kernel, dists, out);
    if (e != cudaSuccess) {
        pnn_main_kernel<<<N_NODES / 64, 256, 65536>>>(dists, out);
    }
}